// round 13
// baseline (speedup 1.0000x reference)
#include <cuda_runtime.h>
#include <cstdint>

// Fixed shapes: B=32, T=1024, D=1024. All GEMM paths are dead code:
// softmax over a singleton axis => every attention weight == 1.0, so
//   context[b,d] = sum_t values[b,t,d],  aw = 1.0,  cov[b,t] = t.
#define BB 32
#define TT 1024
#define DD 1024
#define D4 256                       // float4 per row (4KB rows)
#define NCHUNK 32                    // chunks per batch
#define TC (TT / NCHUNK)             // 32 rows per chunk (128KB contiguous)

// Output layout (98304 floats):
//   [0, B*D)             context   (zeroed in-grid, TMA-bulk-reduce accumulated)
//   [B*D, B*D+B*T)       attention_weights (all 1.0)
//   [B*D+B*T, end)       coverage (cov[b,t] = t)

// Per-batch monotonic tickets (zero-init at load; epoch arithmetic keeps them
// replay-safe without resets). Stride 32 -> one counter per 128B line.
__device__ unsigned int g_cnt[BB * 32];

__device__ __forceinline__ uint32_t smem_u32(const void* p) {
    uint32_t a;
    asm("{ .reg .u64 t; cvta.to.shared.u64 t, %1; cvt.u32.u64 %0, t; }"
        : "=r"(a) : "l"(p));
    return a;
}

// ---- Single kernel: in-grid zero + stream + PIPELINED TMA bulk-reduce ------
// Stream shape (proven ~6.3 TB/s): 1024 slim CTAs, contiguous 128KB per CTA,
// thread-per-float4-column, 8 independent __ldcs loads in flight.
// Epilogue is split: half-1 reduce issues mid-kernel (latency hidden under
// half-2's streaming); only half-2's reduce is an exposed tail.
__global__ __launch_bounds__(256) void stage1_kernel(const float4* __restrict__ vals,
                                                     float* __restrict__ out) {
    __shared__ float4 partA[D4];     // 4KB half-1 partial
    __shared__ float4 partB[D4];     // 4KB half-2 partial
    __shared__ unsigned int s_ticket;

    const int c   = blockIdx.x;      // 0..31 chunk
    const int b   = blockIdx.y;      // 0..31 batch
    const int tid = threadIdx.x;     // 0..255 (one float4 column)

    // ---- Prologue: zero this CTA's 128B context share, take an epoch ticket ----
    if (tid < 8) {
        float4* z = reinterpret_cast<float4*>(out + (size_t)b * DD + (size_t)c * 32);
        z[tid] = make_float4(0.f, 0.f, 0.f, 0.f);
    }
    // aw/cov fill hoisted to the front (off the tail): 8 float4 each per block.
    const int blk = b * NCHUNK + c;  // 0..1023
    if (tid >= 64 && tid < 72) {
        float4* aw4 = reinterpret_cast<float4*>(out + BB * DD);
        aw4[blk * 8 + (tid - 64)] = make_float4(1.f, 1.f, 1.f, 1.f);
    } else if (tid >= 96 && tid < 104) {
        float4* cov4 = reinterpret_cast<float4*>(out + BB * DD + BB * TT);
        const int q = blk * 8 + (tid - 96);      // float4 index into [B,T]
        const int t0 = (q * 4) & (TT - 1);
        cov4[q] = make_float4((float)t0, (float)(t0 + 1), (float)(t0 + 2), (float)(t0 + 3));
    }
    __syncthreads();                 // zeros issued by all 8 lanes
    if (tid == 0) {
        __threadfence();             // zeros globally visible before our ticket
        s_ticket = atomicAdd(&g_cnt[b * 32], 1u);
    }

    const float4* __restrict__ p = vals + ((size_t)b * TT + (size_t)c * TC) * D4 + tid;

    // ---- Half 1: rows [0,16) ----
    {
        float x = 0.f, y = 0.f, z = 0.f, w = 0.f;
#pragma unroll
        for (int i = 0; i < 2; ++i) {
            float4 v0 = __ldcs(&p[0 * (size_t)D4]);
            float4 v1 = __ldcs(&p[1 * (size_t)D4]);
            float4 v2 = __ldcs(&p[2 * (size_t)D4]);
            float4 v3 = __ldcs(&p[3 * (size_t)D4]);
            float4 v4 = __ldcs(&p[4 * (size_t)D4]);
            float4 v5 = __ldcs(&p[5 * (size_t)D4]);
            float4 v6 = __ldcs(&p[6 * (size_t)D4]);
            float4 v7 = __ldcs(&p[7 * (size_t)D4]);
            p += 8 * (size_t)D4;
            x += v0.x; y += v0.y; z += v0.z; w += v0.w;
            x += v1.x; y += v1.y; z += v1.z; w += v1.w;
            x += v2.x; y += v2.y; z += v2.z; w += v2.w;
            x += v3.x; y += v3.y; z += v3.z; w += v3.w;
            x += v4.x; y += v4.y; z += v4.z; w += v4.w;
            x += v5.x; y += v5.y; z += v5.z; w += v5.w;
            x += v6.x; y += v6.y; z += v6.z; w += v6.w;
            x += v7.x; y += v7.y; z += v7.z; w += v7.w;
        }
        partA[tid] = make_float4(x, y, z, w);
    }
    __syncthreads();                 // partA complete; s_ticket visible

    // ---- Issue half-1 reduce (NO wait): latency hides under half 2 ----
    if (tid == 0) {
        // All 32 CTAs of this batch (this epoch) must have zeroed their share.
        // We're ~10us into the kernel; zeros completed in the first ~1us, so
        // this is a single satisfied load in practice.
        const unsigned int target = (s_ticket / NCHUNK + 1u) * NCHUNK;
        while (*(volatile unsigned int*)&g_cnt[b * 32] < target) {}
        __threadfence();             // acquire: peer zeros visible
        asm volatile("fence.proxy.async;" ::: "memory");
        float* dst = out + (size_t)b * DD;
        asm volatile(
            "cp.reduce.async.bulk.global.shared::cta.bulk_group.add.f32 "
            "[%0], [%1], %2;"
            :: "l"(dst), "r"(smem_u32(partA)), "r"((uint32_t)(D4 * sizeof(float4)))
            : "memory");
        asm volatile("cp.async.bulk.commit_group;" ::: "memory");
    }

    // ---- Half 2: rows [16,32) ----
    {
        float x = 0.f, y = 0.f, z = 0.f, w = 0.f;
#pragma unroll
        for (int i = 0; i < 2; ++i) {
            float4 v0 = __ldcs(&p[0 * (size_t)D4]);
            float4 v1 = __ldcs(&p[1 * (size_t)D4]);
            float4 v2 = __ldcs(&p[2 * (size_t)D4]);
            float4 v3 = __ldcs(&p[3 * (size_t)D4]);
            float4 v4 = __ldcs(&p[4 * (size_t)D4]);
            float4 v5 = __ldcs(&p[5 * (size_t)D4]);
            float4 v6 = __ldcs(&p[6 * (size_t)D4]);
            float4 v7 = __ldcs(&p[7 * (size_t)D4]);
            p += 8 * (size_t)D4;
            x += v0.x; y += v0.y; z += v0.z; w += v0.w;
            x += v1.x; y += v1.y; z += v1.z; w += v1.w;
            x += v2.x; y += v2.y; z += v2.z; w += v2.w;
            x += v3.x; y += v3.y; z += v3.z; w += v3.w;
            x += v4.x; y += v4.y; z += v4.z; w += v4.w;
            x += v5.x; y += v5.y; z += v5.z; w += v5.w;
            x += v6.x; y += v6.y; z += v6.z; w += v6.w;
            x += v7.x; y += v7.y; z += v7.z; w += v7.w;
        }
        partB[tid] = make_float4(x, y, z, w);
    }
    __syncthreads();                 // partB complete

    // ---- Final reduce + drain both groups ----
    if (tid == 0) {
        asm volatile("fence.proxy.async;" ::: "memory");
        float* dst = out + (size_t)b * DD;
        asm volatile(
            "cp.reduce.async.bulk.global.shared::cta.bulk_group.add.f32 "
            "[%0], [%1], %2;"
            :: "l"(dst), "r"(smem_u32(partB)), "r"((uint32_t)(D4 * sizeof(float4)))
            : "memory");
        asm volatile("cp.async.bulk.commit_group;" ::: "memory");
        asm volatile("cp.async.bulk.wait_group 0;" ::: "memory");
    }
}

extern "C" void kernel_launch(void* const* d_in, const int* in_sizes, int n_in,
                              void* d_out, int out_size) {
    // Inputs: query, values, W1, b1, W2, b2, W3, b3, V, bV
    const float4* values = (const float4*)d_in[1];
    float* out = (float*)d_out;

    dim3 grid1(NCHUNK, BB);                      // 1024 blocks, one wave
    stage1_kernel<<<grid1, D4>>>(values, out);
}